// round 11
// baseline (speedup 1.0000x reference)
#include <cuda_runtime.h>
#include <cuda_bf16.h>
#include <cstdint>

// ============================================================================
// Policy_Network — collapsed affine form + bulk-copy GEMM pipeline.
// out = [ctx|1] @ E5;  E chain composed on-device.
// R11: R10 base; MMA split passes reordered (hh x4, hl x4, lh x4 per mi) to
// break same-accumulator RAW chains (was 3 dependent HMMAs back-to-back).
// ============================================================================

#define BATCH   8192
#define MAUG    5248          // composed-weight rows (5125 + pad), 41*128
#define ADDROWS 5124

typedef __nv_bfloat16 bf16;

// tile image geometry (must match smem layout below)
#define A_STRIDE 80
#define B_STRIDE 272
#define ACH      20480        // A chunk bytes: 128 rows*80 (hi) + same (lo)
#define BCH      17408        // B chunk bytes: 32 rows*272 (hi) + same (lo)
#define AHALF    10240
#define BHALF    8704
#define STAGE_SZ (ACH + BCH)  // 37888
#define NSTAGE   3
#define SMEM_TOT (128 + NSTAGE * STAGE_SZ)

// ---------------- device scratch: operand images ----------------------------
__device__ __align__(16) char g_ctxA [(size_t)64 * 161 * ACH];   // ctx' A-image
__device__ __align__(16) char g_E1A  [(size_t)41 * 64  * ACH];
__device__ __align__(16) char g_E2A  [(size_t)41 * 32  * ACH];
__device__ __align__(16) char g_E3A  [(size_t)41 * 32  * ACH];
__device__ __align__(16) char g_E4A  [(size_t)41 * 16  * ACH];
__device__ __align__(16) char g_W2aB [(size_t)8  * 64  * BCH];
__device__ __align__(16) char g_W3aB [(size_t)8  * 32  * BCH];
__device__ __align__(16) char g_W4aB [(size_t)4  * 32  * BCH];
__device__ __align__(16) char g_W5B  [(size_t)8  * 16  * BCH];
__device__ __align__(16) char g_E5B  [(size_t)8  * 164 * BCH];

// ---------------- PTX helpers ----------------------------------------------
__device__ __forceinline__ uint32_t smem_u32(const void* p) {
    uint32_t a;
    asm("{ .reg .u64 t; cvta.to.shared.u64 t, %1; cvt.u32.u64 %0, t; }"
        : "=r"(a) : "l"(p));
    return a;
}
__device__ __forceinline__ void mbar_init(uint32_t m, uint32_t cnt) {
    asm volatile("mbarrier.init.shared.b64 [%0], %1;" :: "r"(m), "r"(cnt) : "memory");
}
__device__ __forceinline__ void mbar_expect_tx(uint32_t m, uint32_t bytes) {
    asm volatile("mbarrier.arrive.expect_tx.shared.b64 _, [%0], %1;"
                 :: "r"(m), "r"(bytes) : "memory");
}
__device__ __forceinline__ void mbar_arrive(uint32_t m) {
    asm volatile("mbarrier.arrive.shared.b64 _, [%0];" :: "r"(m) : "memory");
}
__device__ __forceinline__ void mbar_wait(uint32_t m, uint32_t parity) {
    asm volatile(
        "{\n\t.reg .pred P;\n\t"
        "W_%=:\n\t"
        "mbarrier.try_wait.parity.acquire.cta.shared::cta.b64 P, [%0], %1, 0x989680;\n\t"
        "@!P bra W_%=;\n\t"
        "}" :: "r"(m), "r"(parity) : "memory");
}
__device__ __forceinline__ void bulk_g2s(uint32_t dst, const void* src,
                                         uint32_t bytes, uint32_t mbar) {
    asm volatile(
        "cp.async.bulk.shared::cta.global.mbarrier::complete_tx::bytes [%0], [%1], %2, [%3];"
        :: "r"(dst), "l"(src), "r"(bytes), "r"(mbar) : "memory");
}
__device__ __forceinline__ void ldsm4(uint32_t* r, uint32_t a) {
    asm volatile("ldmatrix.sync.aligned.m8n8.x4.shared.b16 {%0,%1,%2,%3}, [%4];"
        : "=r"(r[0]), "=r"(r[1]), "=r"(r[2]), "=r"(r[3]) : "r"(a));
}
__device__ __forceinline__ void ldsm4t(uint32_t* r, uint32_t a) {
    asm volatile("ldmatrix.sync.aligned.m8n8.x4.trans.shared.b16 {%0,%1,%2,%3}, [%4];"
        : "=r"(r[0]), "=r"(r[1]), "=r"(r[2]), "=r"(r[3]) : "r"(a));
}
__device__ __forceinline__ void mma16816(float* d, const uint32_t* a, const uint32_t* b) {
    asm volatile(
        "mma.sync.aligned.m16n8k16.row.col.f32.bf16.bf16.f32 "
        "{%0,%1,%2,%3}, {%4,%5,%6,%7}, {%8,%9}, {%0,%1,%2,%3};"
        : "+f"(d[0]), "+f"(d[1]), "+f"(d[2]), "+f"(d[3])
        : "r"(a[0]), "r"(a[1]), "r"(a[2]), "r"(a[3]), "r"(b[0]), "r"(b[1]));
}
__device__ __forceinline__ void split2(float v, bf16& h, bf16& l) {
    h = __float2bfloat16_rn(v);
    l = __float2bfloat16_rn(v - __bfloat162float(h));
}

// image writers: (m,k) into A-image / (k,n) into B-image; k/n pair-aligned even
__device__ __forceinline__ void writeA2(char* img, int nk, int m, int k,
                                        bf16 h0, bf16 h1, bf16 l0, bf16 l1) {
    char* base = img + (size_t)(m >> 7) * ((size_t)nk * ACH)
               + (size_t)(k >> 5) * ACH + (m & 127) * A_STRIDE + (k & 31) * 2;
    *reinterpret_cast<__nv_bfloat162*>(base)         = __nv_bfloat162(h0, h1);
    *reinterpret_cast<__nv_bfloat162*>(base + AHALF) = __nv_bfloat162(l0, l1);
}
__device__ __forceinline__ void writeB2(char* img, int nkB, int k, int n,
                                        bf16 h0, bf16 h1, bf16 l0, bf16 l1) {
    char* base = img + (size_t)(n >> 7) * ((size_t)nkB * BCH)
               + (size_t)(k >> 5) * BCH + (k & 31) * B_STRIDE + (n & 127) * 2;
    *reinterpret_cast<__nv_bfloat162*>(base)         = __nv_bfloat162(h0, h1);
    *reinterpret_cast<__nv_bfloat162*>(base + BHALF) = __nv_bfloat162(l0, l1);
}

// ---------------- ctx' A-image build ----------------------------------------
__global__ void build_ctx(const float* __restrict__ state,
                          const float* __restrict__ task,
                          const float* __restrict__ action) {
    int r = blockIdx.x, t = threadIdx.x;   // 256 threads
    #pragma unroll 2
    for (int i = t; i < 1024; i += 256) {
        float4 v = reinterpret_cast<const float4*>(state + (size_t)r * 4096)[i];
        bf16 h0,l0,h1,l1,h2,l2,h3,l3;
        split2(v.x,h0,l0); split2(v.y,h1,l1); split2(v.z,h2,l2); split2(v.w,h3,l3);
        writeA2(g_ctxA, 161, r, 4*i,     h0, h1, l0, l1);
        writeA2(g_ctxA, 161, r, 4*i + 2, h2, h3, l2, l3);
    }
    if (t == 0) {
        float4 v = *reinterpret_cast<const float4*>(task + (size_t)r * 4);
        bf16 h0,l0,h1,l1,h2,l2,h3,l3;
        split2(v.x,h0,l0); split2(v.y,h1,l1); split2(v.z,h2,l2); split2(v.w,h3,l3);
        writeA2(g_ctxA, 161, r, 4096, h0, h1, l0, l1);
        writeA2(g_ctxA, 161, r, 4098, h2, h3, l2, l3);
    }
    {
        float4 v = reinterpret_cast<const float4*>(action + (size_t)r * 1024)[t];
        bf16 h0,l0,h1,l1,h2,l2,h3,l3;
        split2(v.x,h0,l0); split2(v.y,h1,l1); split2(v.z,h2,l2); split2(v.w,h3,l3);
        int k = 4100 + 4*t;
        writeA2(g_ctxA, 161, r, k,     h0, h1, l0, l1);
        writeA2(g_ctxA, 161, r, k + 2, h2, h3, l2, l3);
    }
    if (t < 14) {   // k = 5124..5151 as 14 pairs
        bf16 z = __float2bfloat16_rn(0.0f);
        bf16 one = __float2bfloat16_rn(1.0f);
        int k = 5124 + 2*t;
        writeA2(g_ctxA, 161, r, k, (t == 0) ? one : z, z, z, z);
    }
}

// ---------------- E1 = [W1; b1; 0] into A-image (nk=64) ---------------------
__global__ void split_aug(const float* __restrict__ W, const float* __restrict__ b) {
    int m = blockIdx.x;          // 0..5247
    int t = threadIdx.x;         // 512 threads, 4 k each
    int k = t * 4;
    float4 v = make_float4(0.f, 0.f, 0.f, 0.f);
    if (m < ADDROWS)       v = *reinterpret_cast<const float4*>(W + (size_t)m * 2048 + k);
    else if (m == ADDROWS) v = *reinterpret_cast<const float4*>(b + k);
    bf16 h0,l0,h1,l1,h2,l2,h3,l3;
    split2(v.x,h0,l0); split2(v.y,h1,l1); split2(v.z,h2,l2); split2(v.w,h3,l3);
    writeA2(g_E1A, 64, m, k,     h0, h1, l0, l1);
    writeA2(g_E1A, 64, m, k + 2, h2, h3, l2, l3);
}

// ---------------- fused weight splits into B-images -------------------------
struct SplitArgs {
    const float* W[4];
    char* img[4];
    int N[4];
    int nkB[4];
    unsigned long long end4[4];
};

__global__ void split_all(SplitArgs a) {
    unsigned long long e = (unsigned long long)blockIdx.x * 256 + threadIdx.x;
    unsigned long long start = 0;
    #pragma unroll
    for (int s = 0; s < 4; s++) {
        if (e < a.end4[s]) {
            unsigned long long base = (e - start) * 4;
            int N = a.N[s];
            int k = (int)(base / N), n = (int)(base % N);
            float4 v = *reinterpret_cast<const float4*>(a.W[s] + base);
            bf16 h0,l0,h1,l1,h2,l2,h3,l3;
            split2(v.x,h0,l0); split2(v.y,h1,l1);
            split2(v.z,h2,l2); split2(v.w,h3,l3);
            writeB2(a.img[s], a.nkB[s], k, n,     h0, h1, l0, l1);
            writeB2(a.img[s], a.nkB[s], k, n + 2, h2, h3, l2, l3);
            return;
        }
        start = a.end4[s];
    }
}

// ---------------- bulk-fed HMMA split GEMM, full/empty mbarriers ------------
__device__ __forceinline__ float addval(const float* AddW, const float* Addb,
                                        int r, int c, int N) {
    if (AddW && r < ADDROWS) return AddW[(size_t)r * N + c];
    if (Addb && r == ADDROWS) return Addb[c];
    return 0.0f;
}

__global__ __launch_bounds__(256, 2)
void gemm_bulk(const char* __restrict__ Aimg, const char* __restrict__ Bimg,
               int nk, int nkB, int N,
               const float* __restrict__ AddW, const float* __restrict__ Addb,
               float* __restrict__ Cf,
               char* __restrict__ outA, int KCo,
               char* __restrict__ outB, int KCb) {
    extern __shared__ char smem_raw[];
    const uint32_t sb = smem_u32(smem_raw);
    const uint32_t stages = sb + 128;
    // full[s] at sb + s*8 ; empty[s] at sb + 64 + s*8

    const int tid  = threadIdx.x;
    const int wid  = tid >> 5;
    const int lane = tid & 31;
    const int warp_m = (wid & 1) * 64;
    const int warp_n = (wid >> 1) * 32;
    const int block_row = blockIdx.y * 128;
    const int block_col = blockIdx.x * 128;

    const char* Abase = Aimg + (size_t)blockIdx.y * ((size_t)nk  * ACH);
    const char* Bbase = Bimg + (size_t)blockIdx.x * ((size_t)nkB * BCH);

    if (tid == 0) {
        #pragma unroll
        for (int s = 0; s < NSTAGE; s++) {
            mbar_init(sb + s * 8, 1);        // full: one bulk-pair tx
            mbar_init(sb + 64 + s * 8, 8);   // empty: one arrive per warp
        }
    }
    __syncthreads();

    if (tid == 0) {
        #pragma unroll
        for (int s = 0; s < NSTAGE; s++) {
            if (s < nk) {
                uint32_t mb = sb + s * 8;
                mbar_expect_tx(mb, STAGE_SZ);
                bulk_g2s(stages + s * STAGE_SZ,       Abase + (size_t)s * ACH, ACH, mb);
                bulk_g2s(stages + s * STAGE_SZ + ACH, Bbase + (size_t)s * BCH, BCH, mb);
            }
        }
    }

    float acc[64];
    #pragma unroll
    for (int i = 0; i < 64; i++) acc[i] = 0.0f;

    const int lr = lane & 15;
    const int lc = (lane >> 4) << 3;

    int stage = 0;
    uint32_t par = 0;
    for (int it = 0; it < nk; ++it) {
        mbar_wait(sb + stage * 8, par);      // full[stage]

        const uint32_t sA = stages + stage * STAGE_SZ;
        const uint32_t sB = sA + ACH;

        #pragma unroll
        for (int k2 = 0; k2 < 2; k2++) {
            uint32_t bh[8], bl[8];
            #pragma unroll
            for (int nb = 0; nb < 2; nb++) {
                uint32_t addr = sB + (k2 * 16 + lr) * B_STRIDE
                              + (warp_n + nb * 16 + lc) * 2;
                ldsm4t(&bh[nb * 4], addr);
                ldsm4t(&bl[nb * 4], addr + BHALF);
            }
            #pragma unroll
            for (int mi = 0; mi < 4; mi++) {
                uint32_t ah[4], al[4];
                uint32_t addr = sA + (warp_m + mi * 16 + lr) * A_STRIDE
                              + (k2 * 16 + lc) * 2;
                ldsm4(ah, addr);
                ldsm4(al, addr + AHALF);
                // split passes separated: same-accumulator reuse distance 4
                #pragma unroll
                for (int ni = 0; ni < 4; ni++)
                    mma16816(acc + (mi * 4 + ni) * 4, ah, &bh[ni * 2]);
                #pragma unroll
                for (int ni = 0; ni < 4; ni++)
                    mma16816(acc + (mi * 4 + ni) * 4, ah, &bl[ni * 2]);
                #pragma unroll
                for (int ni = 0; ni < 4; ni++)
                    mma16816(acc + (mi * 4 + ni) * 4, al, &bh[ni * 2]);
            }
        }

        // this warp is done with the buffer
        if (lane == 0) mbar_arrive(sb + 64 + stage * 8);

        // producer: recycle this stage for chunk it+NSTAGE once all warps done
        if (tid == 0 && it + NSTAGE < nk) {
            mbar_wait(sb + 64 + stage * 8, par);   // empty[stage], same parity
            uint32_t mb = sb + stage * 8;
            mbar_expect_tx(mb, STAGE_SZ);
            bulk_g2s(stages + stage * STAGE_SZ,
                     Abase + (size_t)(it + NSTAGE) * ACH, ACH, mb);
            bulk_g2s(stages + stage * STAGE_SZ + ACH,
                     Bbase + (size_t)(it + NSTAGE) * BCH, BCH, mb);
        }

        if (++stage == NSTAGE) { stage = 0; par ^= 1; }
    }

    // ---- epilogue (no cross-warp smem dependency) ----
    #pragma unroll
    for (int mi = 0; mi < 4; mi++) {
        #pragma unroll
        for (int ni = 0; ni < 4; ni++) {
            const float* d = acc + (mi * 4 + ni) * 4;
            int r0 = block_row + warp_m + mi * 16 + (lane >> 2);
            int c0 = block_col + warp_n + ni * 8 + (lane & 3) * 2;
            if (Cf) {
                *reinterpret_cast<float2*>(Cf + (size_t)r0 * N + c0) =
                    make_float2(d[0], d[1]);
                *reinterpret_cast<float2*>(Cf + (size_t)(r0 + 8) * N + c0) =
                    make_float2(d[2], d[3]);
            } else {
                float v00 = d[0] + addval(AddW, Addb, r0,     c0,     N);
                float v01 = d[1] + addval(AddW, Addb, r0,     c0 + 1, N);
                float v10 = d[2] + addval(AddW, Addb, r0 + 8, c0,     N);
                float v11 = d[3] + addval(AddW, Addb, r0 + 8, c0 + 1, N);
                bf16 h0,l0,h1,l1,h2,l2,h3,l3;
                split2(v00,h0,l0); split2(v01,h1,l1);
                split2(v10,h2,l2); split2(v11,h3,l3);
                if (outA) {
                    writeA2(outA, KCo, r0,     c0, h0, h1, l0, l1);
                    writeA2(outA, KCo, r0 + 8, c0, h2, h3, l2, l3);
                } else {
                    writeB2(outB, KCb, r0,     c0, h0, h1, l0, l1);
                    writeB2(outB, KCb, r0 + 8, c0, h2, h3, l2, l3);
                }
            }
        }
    }
}

// ---------------- host ------------------------------------------------------
template <typename T>
static T* sym_addr(const void* symbol) {
    void* p = nullptr;
    cudaGetSymbolAddress(&p, symbol);
    return reinterpret_cast<T*>(p);
}

extern "C" void kernel_launch(void* const* d_in, const int* in_sizes, int n_in,
                              void* d_out, int out_size) {
    const float* state  = (const float*)d_in[0];
    const float* action = (const float*)d_in[1];
    const float* task   = (const float*)d_in[2];
    // d_in[3..18]: dead cx branch weights
    const float* W_l1 = (const float*)d_in[19];
    const float* b_l1 = (const float*)d_in[20];
    const float* W_l2 = (const float*)d_in[21];
    const float* b_l2 = (const float*)d_in[22];
    const float* W_l3 = (const float*)d_in[23];
    const float* b_l3 = (const float*)d_in[24];
    const float* W_l4 = (const float*)d_in[25];
    const float* b_l4 = (const float*)d_in[26];
    const float* W_l5 = (const float*)d_in[27];
    const float* b_l5 = (const float*)d_in[28];
    float* out = (float*)d_out;

    cudaFuncSetAttribute(gemm_bulk,
                         cudaFuncAttributeMaxDynamicSharedMemorySize, SMEM_TOT);

    char* ctxA = sym_addr<char>(g_ctxA);
    char* e1A  = sym_addr<char>(g_E1A);
    char* e2A  = sym_addr<char>(g_E2A);
    char* e3A  = sym_addr<char>(g_E3A);
    char* e4A  = sym_addr<char>(g_E4A);
    char* w2aB = sym_addr<char>(g_W2aB);
    char* w3aB = sym_addr<char>(g_W3aB);
    char* w4aB = sym_addr<char>(g_W4aB);
    char* w5B  = sym_addr<char>(g_W5B);
    char* e5B  = sym_addr<char>(g_E5B);

    // 0: ctx' A-image
    build_ctx<<<BATCH, 256>>>(state, task, action);
    // 1: E1 A-image
    split_aug<<<MAUG, 512>>>(W_l1, b_l1);
    // 2: B-images of W2a, W3a, W4a, W5
    {
        SplitArgs sa;
        const float* Ws[4] = {W_l2, W_l3, W_l4, W_l5};
        char* imgs[4] = {w2aB, w3aB, w4aB, w5B};
        int Ns[4]   = {1024, 1024, 512, 1024};
        int nkBs[4] = {64, 32, 32, 16};
        const unsigned long long sz4[4] = {
            2048ull * 1024 / 4, 1024ull * 1024 / 4,
            1024ull * 512 / 4,  512ull * 1024 / 4 };
        unsigned long long cum = 0;
        for (int s = 0; s < 4; s++) {
            sa.W[s] = Ws[s]; sa.img[s] = imgs[s];
            sa.N[s] = Ns[s]; sa.nkB[s] = nkBs[s];
            cum += sz4[s]; sa.end4[s] = cum;
        }
        split_all<<<(unsigned)((cum + 255) / 256), 256>>>(sa);
    }

    // 3..6: weight-chain compositions (M = 5248)
    gemm_bulk<<<dim3(8, 41), 256, SMEM_TOT>>>(
        e1A, w2aB, 64, 64, 1024,
        W_l2 + (size_t)2048 * 1024, b_l2, nullptr, e2A, 32, nullptr, 0);
    gemm_bulk<<<dim3(8, 41), 256, SMEM_TOT>>>(
        e2A, w3aB, 32, 32, 1024,
        W_l3 + (size_t)1024 * 1024, b_l3, nullptr, e3A, 32, nullptr, 0);
    gemm_bulk<<<dim3(4, 41), 256, SMEM_TOT>>>(
        e3A, w4aB, 32, 32, 512,
        W_l4 + (size_t)1024 * 512, b_l4, nullptr, e4A, 16, nullptr, 0);
    gemm_bulk<<<dim3(8, 41), 256, SMEM_TOT>>>(
        e4A, w5B, 16, 16, 1024,
        nullptr, b_l5, nullptr, nullptr, 0, e5B, 164);

    // 7: final GEMM  out = ctx' @ E5  (bias via augmented column; K=5152)
    gemm_bulk<<<dim3(8, BATCH / 128), 256, SMEM_TOT>>>(
        ctxA, e5B, 161, 164, 1024,
        nullptr, nullptr, out, nullptr, 0, nullptr, 0);
}

// round 12
// speedup vs baseline: 1.2989x; 1.2989x over previous
#include <cuda_runtime.h>
#include <cuda_bf16.h>
#include <cstdint>

// ============================================================================
// Policy_Network — collapsed affine form, bottleneck-aware parenthesization.
//   out = ctx' @ E5 = (ctx' @ E4) @ W5 + b5      (E4 is 512 wide: cheapest path)
//   E2 = E1@W2a + aug(W2b,b2); E3 = E2@W3a + aug; E4 = E3@W4a + aug
// GEMMs: verified bulk-fed bf16 hi/lo split HMMA core (R10).
// FLOPs: 271 G-MMA vs 391 (R11) vs 1368 (naive forward).
// ============================================================================

#define BATCH   8192
#define MAUG    5248          // composed-weight rows (5125 + pad), 41*128
#define ADDROWS 5124

typedef __nv_bfloat16 bf16;

// tile image geometry (must match smem layout below)
#define A_STRIDE 80
#define B_STRIDE 272
#define ACH      20480        // A chunk bytes: 128 rows*80 (hi) + same (lo)
#define BCH      17408        // B chunk bytes: 32 rows*272 (hi) + same (lo)
#define AHALF    10240
#define BHALF    8704
#define STAGE_SZ (ACH + BCH)  // 37888
#define NSTAGE   3
#define SMEM_TOT (128 + NSTAGE * STAGE_SZ)

// ---------------- device scratch: operand images ----------------------------
__device__ __align__(16) char g_ctxA [(size_t)64 * 161 * ACH];   // ctx' A-image
__device__ __align__(16) char g_E1A  [(size_t)41 * 64  * ACH];
__device__ __align__(16) char g_E2A  [(size_t)41 * 32  * ACH];
__device__ __align__(16) char g_E3A  [(size_t)41 * 32  * ACH];
__device__ __align__(16) char g_E4B  [(size_t)4  * 164 * BCH];   // E4 as B-image
__device__ __align__(16) char g_GA   [(size_t)64 * 16  * ACH];   // G = ctx'@E4
__device__ __align__(16) char g_W2aB [(size_t)8  * 64  * BCH];
__device__ __align__(16) char g_W3aB [(size_t)8  * 32  * BCH];
__device__ __align__(16) char g_W4aB [(size_t)4  * 32  * BCH];
__device__ __align__(16) char g_W5B  [(size_t)8  * 16  * BCH];

// ---------------- PTX helpers ----------------------------------------------
__device__ __forceinline__ uint32_t smem_u32(const void* p) {
    uint32_t a;
    asm("{ .reg .u64 t; cvta.to.shared.u64 t, %1; cvt.u32.u64 %0, t; }"
        : "=r"(a) : "l"(p));
    return a;
}
__device__ __forceinline__ void mbar_init(uint32_t m, uint32_t cnt) {
    asm volatile("mbarrier.init.shared.b64 [%0], %1;" :: "r"(m), "r"(cnt) : "memory");
}
__device__ __forceinline__ void mbar_expect_tx(uint32_t m, uint32_t bytes) {
    asm volatile("mbarrier.arrive.expect_tx.shared.b64 _, [%0], %1;"
                 :: "r"(m), "r"(bytes) : "memory");
}
__device__ __forceinline__ void mbar_arrive(uint32_t m) {
    asm volatile("mbarrier.arrive.shared.b64 _, [%0];" :: "r"(m) : "memory");
}
__device__ __forceinline__ void mbar_wait(uint32_t m, uint32_t parity) {
    asm volatile(
        "{\n\t.reg .pred P;\n\t"
        "W_%=:\n\t"
        "mbarrier.try_wait.parity.acquire.cta.shared::cta.b64 P, [%0], %1, 0x989680;\n\t"
        "@!P bra W_%=;\n\t"
        "}" :: "r"(m), "r"(parity) : "memory");
}
__device__ __forceinline__ void bulk_g2s(uint32_t dst, const void* src,
                                         uint32_t bytes, uint32_t mbar) {
    asm volatile(
        "cp.async.bulk.shared::cta.global.mbarrier::complete_tx::bytes [%0], [%1], %2, [%3];"
        :: "r"(dst), "l"(src), "r"(bytes), "r"(mbar) : "memory");
}
__device__ __forceinline__ void ldsm4(uint32_t* r, uint32_t a) {
    asm volatile("ldmatrix.sync.aligned.m8n8.x4.shared.b16 {%0,%1,%2,%3}, [%4];"
        : "=r"(r[0]), "=r"(r[1]), "=r"(r[2]), "=r"(r[3]) : "r"(a));
}
__device__ __forceinline__ void ldsm4t(uint32_t* r, uint32_t a) {
    asm volatile("ldmatrix.sync.aligned.m8n8.x4.trans.shared.b16 {%0,%1,%2,%3}, [%4];"
        : "=r"(r[0]), "=r"(r[1]), "=r"(r[2]), "=r"(r[3]) : "r"(a));
}
__device__ __forceinline__ void mma16816(float* d, const uint32_t* a, const uint32_t* b) {
    asm volatile(
        "mma.sync.aligned.m16n8k16.row.col.f32.bf16.bf16.f32 "
        "{%0,%1,%2,%3}, {%4,%5,%6,%7}, {%8,%9}, {%0,%1,%2,%3};"
        : "+f"(d[0]), "+f"(d[1]), "+f"(d[2]), "+f"(d[3])
        : "r"(a[0]), "r"(a[1]), "r"(a[2]), "r"(a[3]), "r"(b[0]), "r"(b[1]));
}
__device__ __forceinline__ void split2(float v, bf16& h, bf16& l) {
    h = __float2bfloat16_rn(v);
    l = __float2bfloat16_rn(v - __bfloat162float(h));
}

// image writers: (m,k) into A-image / (k,n) into B-image; k/n pair-aligned even
__device__ __forceinline__ void writeA2(char* img, int nk, int m, int k,
                                        bf16 h0, bf16 h1, bf16 l0, bf16 l1) {
    char* base = img + (size_t)(m >> 7) * ((size_t)nk * ACH)
               + (size_t)(k >> 5) * ACH + (m & 127) * A_STRIDE + (k & 31) * 2;
    *reinterpret_cast<__nv_bfloat162*>(base)         = __nv_bfloat162(h0, h1);
    *reinterpret_cast<__nv_bfloat162*>(base + AHALF) = __nv_bfloat162(l0, l1);
}
__device__ __forceinline__ void writeB2(char* img, int nkB, int k, int n,
                                        bf16 h0, bf16 h1, bf16 l0, bf16 l1) {
    char* base = img + (size_t)(n >> 7) * ((size_t)nkB * BCH)
               + (size_t)(k >> 5) * BCH + (k & 31) * B_STRIDE + (n & 127) * 2;
    *reinterpret_cast<__nv_bfloat162*>(base)         = __nv_bfloat162(h0, h1);
    *reinterpret_cast<__nv_bfloat162*>(base + BHALF) = __nv_bfloat162(l0, l1);
}

// ---------------- ctx' A-image build ----------------------------------------
__global__ void build_ctx(const float* __restrict__ state,
                          const float* __restrict__ task,
                          const float* __restrict__ action) {
    int r = blockIdx.x, t = threadIdx.x;   // 256 threads
    #pragma unroll 2
    for (int i = t; i < 1024; i += 256) {
        float4 v = reinterpret_cast<const float4*>(state + (size_t)r * 4096)[i];
        bf16 h0,l0,h1,l1,h2,l2,h3,l3;
        split2(v.x,h0,l0); split2(v.y,h1,l1); split2(v.z,h2,l2); split2(v.w,h3,l3);
        writeA2(g_ctxA, 161, r, 4*i,     h0, h1, l0, l1);
        writeA2(g_ctxA, 161, r, 4*i + 2, h2, h3, l2, l3);
    }
    if (t == 0) {
        float4 v = *reinterpret_cast<const float4*>(task + (size_t)r * 4);
        bf16 h0,l0,h1,l1,h2,l2,h3,l3;
        split2(v.x,h0,l0); split2(v.y,h1,l1); split2(v.z,h2,l2); split2(v.w,h3,l3);
        writeA2(g_ctxA, 161, r, 4096, h0, h1, l0, l1);
        writeA2(g_ctxA, 161, r, 4098, h2, h3, l2, l3);
    }
    {
        float4 v = reinterpret_cast<const float4*>(action + (size_t)r * 1024)[t];
        bf16 h0,l0,h1,l1,h2,l2,h3,l3;
        split2(v.x,h0,l0); split2(v.y,h1,l1); split2(v.z,h2,l2); split2(v.w,h3,l3);
        int k = 4100 + 4*t;
        writeA2(g_ctxA, 161, r, k,     h0, h1, l0, l1);
        writeA2(g_ctxA, 161, r, k + 2, h2, h3, l2, l3);
    }
    if (t < 14) {   // k = 5124..5151 as 14 pairs
        bf16 z = __float2bfloat16_rn(0.0f);
        bf16 one = __float2bfloat16_rn(1.0f);
        int k = 5124 + 2*t;
        writeA2(g_ctxA, 161, r, k, (t == 0) ? one : z, z, z, z);
    }
}

// ---------------- E1 = [W1; b1; 0] into A-image (nk=64) ---------------------
__global__ void split_aug(const float* __restrict__ W, const float* __restrict__ b) {
    int m = blockIdx.x;          // 0..5247
    int t = threadIdx.x;         // 512 threads, 4 k each
    int k = t * 4;
    float4 v = make_float4(0.f, 0.f, 0.f, 0.f);
    if (m < ADDROWS)       v = *reinterpret_cast<const float4*>(W + (size_t)m * 2048 + k);
    else if (m == ADDROWS) v = *reinterpret_cast<const float4*>(b + k);
    bf16 h0,l0,h1,l1,h2,l2,h3,l3;
    split2(v.x,h0,l0); split2(v.y,h1,l1); split2(v.z,h2,l2); split2(v.w,h3,l3);
    writeA2(g_E1A, 64, m, k,     h0, h1, l0, l1);
    writeA2(g_E1A, 64, m, k + 2, h2, h3, l2, l3);
}

// ---------------- fused weight splits into B-images -------------------------
struct SplitArgs {
    const float* W[4];
    char* img[4];
    int N[4];
    int nkB[4];
    unsigned long long end4[4];
};

__global__ void split_all(SplitArgs a) {
    unsigned long long e = (unsigned long long)blockIdx.x * 256 + threadIdx.x;
    unsigned long long start = 0;
    #pragma unroll
    for (int s = 0; s < 4; s++) {
        if (e < a.end4[s]) {
            unsigned long long base = (e - start) * 4;
            int N = a.N[s];
            int k = (int)(base / N), n = (int)(base % N);
            float4 v = *reinterpret_cast<const float4*>(a.W[s] + base);
            bf16 h0,l0,h1,l1,h2,l2,h3,l3;
            split2(v.x,h0,l0); split2(v.y,h1,l1);
            split2(v.z,h2,l2); split2(v.w,h3,l3);
            writeB2(a.img[s], a.nkB[s], k, n,     h0, h1, l0, l1);
            writeB2(a.img[s], a.nkB[s], k, n + 2, h2, h3, l2, l3);
            return;
        }
        start = a.end4[s];
    }
}

// ---------------- bulk-fed HMMA split GEMM, full/empty mbarriers ------------
__device__ __forceinline__ float addval(const float* AddW, const float* Addb,
                                        int r, int c, int N) {
    if (AddW && r < ADDROWS) return AddW[(size_t)r * N + c];
    if (Addb && r == ADDROWS) return Addb[c];
    return 0.0f;
}

__global__ __launch_bounds__(256, 2)
void gemm_bulk(const char* __restrict__ Aimg, const char* __restrict__ Bimg,
               int nk, int nkB, int N,
               const float* __restrict__ AddW, const float* __restrict__ Addb,
               const float* __restrict__ BiasN,   // per-column bias (fp32 out)
               float* __restrict__ Cf,
               char* __restrict__ outA, int KCo,
               char* __restrict__ outB, int KCb) {
    extern __shared__ char smem_raw[];
    const uint32_t sb = smem_u32(smem_raw);
    const uint32_t stages = sb + 128;
    // full[s] at sb + s*8 ; empty[s] at sb + 64 + s*8

    const int tid  = threadIdx.x;
    const int wid  = tid >> 5;
    const int lane = tid & 31;
    const int warp_m = (wid & 1) * 64;
    const int warp_n = (wid >> 1) * 32;
    const int block_row = blockIdx.y * 128;
    const int block_col = blockIdx.x * 128;

    const char* Abase = Aimg + (size_t)blockIdx.y * ((size_t)nk  * ACH);
    const char* Bbase = Bimg + (size_t)blockIdx.x * ((size_t)nkB * BCH);

    if (tid == 0) {
        #pragma unroll
        for (int s = 0; s < NSTAGE; s++) {
            mbar_init(sb + s * 8, 1);        // full: one bulk-pair tx
            mbar_init(sb + 64 + s * 8, 8);   // empty: one arrive per warp
        }
    }
    __syncthreads();

    if (tid == 0) {
        #pragma unroll
        for (int s = 0; s < NSTAGE; s++) {
            if (s < nk) {
                uint32_t mb = sb + s * 8;
                mbar_expect_tx(mb, STAGE_SZ);
                bulk_g2s(stages + s * STAGE_SZ,       Abase + (size_t)s * ACH, ACH, mb);
                bulk_g2s(stages + s * STAGE_SZ + ACH, Bbase + (size_t)s * BCH, BCH, mb);
            }
        }
    }

    float acc[64];
    #pragma unroll
    for (int i = 0; i < 64; i++) acc[i] = 0.0f;

    const int lr = lane & 15;
    const int lc = (lane >> 4) << 3;

    int stage = 0;
    uint32_t par = 0;
    for (int it = 0; it < nk; ++it) {
        mbar_wait(sb + stage * 8, par);      // full[stage]

        const uint32_t sA = stages + stage * STAGE_SZ;
        const uint32_t sB = sA + ACH;

        #pragma unroll
        for (int k2 = 0; k2 < 2; k2++) {
            uint32_t bh[8], bl[8];
            #pragma unroll
            for (int nb = 0; nb < 2; nb++) {
                uint32_t addr = sB + (k2 * 16 + lr) * B_STRIDE
                              + (warp_n + nb * 16 + lc) * 2;
                ldsm4t(&bh[nb * 4], addr);
                ldsm4t(&bl[nb * 4], addr + BHALF);
            }
            #pragma unroll
            for (int mi = 0; mi < 4; mi++) {
                uint32_t ah[4], al[4];
                uint32_t addr = sA + (warp_m + mi * 16 + lr) * A_STRIDE
                              + (k2 * 16 + lc) * 2;
                ldsm4(ah, addr);
                ldsm4(al, addr + AHALF);
                #pragma unroll
                for (int ni = 0; ni < 4; ni++) {
                    float* d = acc + (mi * 4 + ni) * 4;
                    mma16816(d, ah, &bh[ni * 2]);
                    mma16816(d, ah, &bl[ni * 2]);
                    mma16816(d, al, &bh[ni * 2]);
                }
            }
        }

        // this warp is done with the buffer
        if (lane == 0) mbar_arrive(sb + 64 + stage * 8);

        // producer: recycle this stage for chunk it+NSTAGE once all warps done
        if (tid == 0 && it + NSTAGE < nk) {
            mbar_wait(sb + 64 + stage * 8, par);   // empty[stage], same parity
            uint32_t mb = sb + stage * 8;
            mbar_expect_tx(mb, STAGE_SZ);
            bulk_g2s(stages + stage * STAGE_SZ,
                     Abase + (size_t)(it + NSTAGE) * ACH, ACH, mb);
            bulk_g2s(stages + stage * STAGE_SZ + ACH,
                     Bbase + (size_t)(it + NSTAGE) * BCH, BCH, mb);
        }

        if (++stage == NSTAGE) { stage = 0; par ^= 1; }
    }

    // ---- epilogue (no cross-warp smem dependency) ----
    #pragma unroll
    for (int mi = 0; mi < 4; mi++) {
        #pragma unroll
        for (int ni = 0; ni < 4; ni++) {
            const float* d = acc + (mi * 4 + ni) * 4;
            int r0 = block_row + warp_m + mi * 16 + (lane >> 2);
            int c0 = block_col + warp_n + ni * 8 + (lane & 3) * 2;
            if (Cf) {
                float b0 = BiasN ? BiasN[c0]     : 0.0f;
                float b1 = BiasN ? BiasN[c0 + 1] : 0.0f;
                *reinterpret_cast<float2*>(Cf + (size_t)r0 * N + c0) =
                    make_float2(d[0] + b0, d[1] + b1);
                *reinterpret_cast<float2*>(Cf + (size_t)(r0 + 8) * N + c0) =
                    make_float2(d[2] + b0, d[3] + b1);
            } else {
                float v00 = d[0] + addval(AddW, Addb, r0,     c0,     N);
                float v01 = d[1] + addval(AddW, Addb, r0,     c0 + 1, N);
                float v10 = d[2] + addval(AddW, Addb, r0 + 8, c0,     N);
                float v11 = d[3] + addval(AddW, Addb, r0 + 8, c0 + 1, N);
                bf16 h0,l0,h1,l1,h2,l2,h3,l3;
                split2(v00,h0,l0); split2(v01,h1,l1);
                split2(v10,h2,l2); split2(v11,h3,l3);
                if (outA) {
                    writeA2(outA, KCo, r0,     c0, h0, h1, l0, l1);
                    writeA2(outA, KCo, r0 + 8, c0, h2, h3, l2, l3);
                } else {
                    writeB2(outB, KCb, r0,     c0, h0, h1, l0, l1);
                    writeB2(outB, KCb, r0 + 8, c0, h2, h3, l2, l3);
                }
            }
        }
    }
}

// ---------------- host ------------------------------------------------------
template <typename T>
static T* sym_addr(const void* symbol) {
    void* p = nullptr;
    cudaGetSymbolAddress(&p, symbol);
    return reinterpret_cast<T*>(p);
}

extern "C" void kernel_launch(void* const* d_in, const int* in_sizes, int n_in,
                              void* d_out, int out_size) {
    const float* state  = (const float*)d_in[0];
    const float* action = (const float*)d_in[1];
    const float* task   = (const float*)d_in[2];
    // d_in[3..18]: dead cx branch weights
    const float* W_l1 = (const float*)d_in[19];
    const float* b_l1 = (const float*)d_in[20];
    const float* W_l2 = (const float*)d_in[21];
    const float* b_l2 = (const float*)d_in[22];
    const float* W_l3 = (const float*)d_in[23];
    const float* b_l3 = (const float*)d_in[24];
    const float* W_l4 = (const float*)d_in[25];
    const float* b_l4 = (const float*)d_in[26];
    const float* W_l5 = (const float*)d_in[27];
    const float* b_l5 = (const float*)d_in[28];
    float* out = (float*)d_out;

    cudaFuncSetAttribute(gemm_bulk,
                         cudaFuncAttributeMaxDynamicSharedMemorySize, SMEM_TOT);

    char* ctxA = sym_addr<char>(g_ctxA);
    char* e1A  = sym_addr<char>(g_E1A);
    char* e2A  = sym_addr<char>(g_E2A);
    char* e3A  = sym_addr<char>(g_E3A);
    char* e4B  = sym_addr<char>(g_E4B);
    char* gA   = sym_addr<char>(g_GA);
    char* w2aB = sym_addr<char>(g_W2aB);
    char* w3aB = sym_addr<char>(g_W3aB);
    char* w4aB = sym_addr<char>(g_W4aB);
    char* w5B  = sym_addr<char>(g_W5B);

    // 0: ctx' A-image
    build_ctx<<<BATCH, 256>>>(state, task, action);
    // 1: E1 A-image
    split_aug<<<MAUG, 512>>>(W_l1, b_l1);
    // 2: B-images of W2a, W3a, W4a, W5
    {
        SplitArgs sa;
        const float* Ws[4] = {W_l2, W_l3, W_l4, W_l5};
        char* imgs[4] = {w2aB, w3aB, w4aB, w5B};
        int Ns[4]   = {1024, 1024, 512, 1024};
        int nkBs[4] = {64, 32, 32, 16};
        const unsigned long long sz4[4] = {
            2048ull * 1024 / 4, 1024ull * 1024 / 4,
            1024ull * 512 / 4,  512ull * 1024 / 4 };
        unsigned long long cum = 0;
        for (int s = 0; s < 4; s++) {
            sa.W[s] = Ws[s]; sa.img[s] = imgs[s];
            sa.N[s] = Ns[s]; sa.nkB[s] = nkBs[s];
            cum += sz4[s]; sa.end4[s] = cum;
        }
        split_all<<<(unsigned)((cum + 255) / 256), 256>>>(sa);
    }

    // 3: E2 = E1@W2a + aug(W2b,b2)          [A-image, 32 chunks]
    gemm_bulk<<<dim3(8, 41), 256, SMEM_TOT>>>(
        e1A, w2aB, 64, 64, 1024,
        W_l2 + (size_t)2048 * 1024, b_l2, nullptr, nullptr, e2A, 32, nullptr, 0);
    // 4: E3 = E2@W3a + aug(W3b,b3)          [A-image, 32 chunks]
    gemm_bulk<<<dim3(8, 41), 256, SMEM_TOT>>>(
        e2A, w3aB, 32, 32, 1024,
        W_l3 + (size_t)1024 * 1024, b_l3, nullptr, nullptr, e3A, 32, nullptr, 0);
    // 5: E4 = E3@W4a + aug(W4b,b4)          [B-image, nkB=164, N=512]
    gemm_bulk<<<dim3(4, 41), 256, SMEM_TOT>>>(
        e3A, w4aB, 32, 32, 512,
        W_l4 + (size_t)1024 * 512, b_l4, nullptr, nullptr, nullptr, 0, e4B, 164);
    // 6: G = ctx'@E4                        [A-image, 16 chunks, N=512, K=5152]
    gemm_bulk<<<dim3(4, BATCH / 128), 256, SMEM_TOT>>>(
        ctxA, e4B, 161, 164, 512,
        nullptr, nullptr, nullptr, nullptr, gA, 16, nullptr, 0);
    // 7: out = G@W5 + b5                    [fp32, per-column bias, K=512]
    gemm_bulk<<<dim3(8, BATCH / 128), 256, SMEM_TOT>>>(
        gA, w5B, 16, 16, 1024,
        nullptr, nullptr, b_l5, out, nullptr, 0, nullptr, 0);
}